// round 2
// baseline (speedup 1.0000x reference)
#include <cuda_runtime.h>
#include <math.h>

#define KNN 20
#define THREADS 256
#define TILE 8192   // db points per smem tile (float4 -> 128KB)

// per-block partial sums: [side][b][chunk] flattened; sized generously
__device__ float g_partials[1024];

__global__ void __launch_bounds__(THREADS, 1) knn_kernel(
    const float* __restrict__ xyz1, const float* __restrict__ xyz2,
    const float* __restrict__ hsv1, const float* __restrict__ hsv2,
    const float* __restrict__ nrm1, const float* __restrict__ nrm2,
    const float* __restrict__ res1, const float* __restrict__ res2,
    const float* __restrict__ R12,  const float* __restrict__ t12,
    const float* __restrict__ R21,  const float* __restrict__ t21,
    const int* __restrict__ npts1,  const int* __restrict__ npts2,
    int B, int P)
{
    extern __shared__ float4 tile[];
    const int side  = blockIdx.z;
    const int b     = blockIdx.y;
    const int chunk = blockIdx.x;
    const int tid   = threadIdx.x;

    const float *q_xyz, *q_hsv, *q_nrm, *q_res;
    const float *d_xyzp, *d_hsv, *d_nrm, *d_res;
    const float *R, *T;
    int nq, ndb;
    const size_t o3 = (size_t)b * P * 3;
    const size_t o1 = (size_t)b * P;
    if (side == 0) {
        // queries = cloud 1, db = cloud 2 transformed into frame 1 via R12,t12
        q_xyz = xyz1 + o3; q_hsv = hsv1 + o3; q_nrm = nrm1 + o3; q_res = res1 + o1;
        d_xyzp = xyz2 + o3; d_hsv = hsv2 + o3; d_nrm = nrm2 + o3; d_res = res2 + o1;
        R = R12 + b * 9; T = t12 + b * 3;
        nq = npts1[b]; ndb = npts2[b];
    } else {
        q_xyz = xyz2 + o3; q_hsv = hsv2 + o3; q_nrm = nrm2 + o3; q_res = res2 + o1;
        d_xyzp = xyz1 + o3; d_hsv = hsv1 + o3; d_nrm = nrm1 + o3; d_res = res1 + o1;
        R = R21 + b * 9; T = t21 + b * 3;
        nq = npts2[b]; ndb = npts1[b];
    }

    const float r00 = R[0], r01 = R[1], r02 = R[2];
    const float r10 = R[3], r11 = R[4], r12_ = R[5];
    const float r20 = R[6], r21_ = R[7], r22 = R[8];
    const float t0 = T[0], t1 = T[1], t2 = T[2];

    const int q = chunk * THREADS + tid;
    const bool active = (q < nq);

    float kd[KNN]; int ki[KNN];
    #pragma unroll
    for (int s = 0; s < KNN; ++s) { kd[s] = 1e30f; ki[s] = 0; }

    float qx = 0.f, qy = 0.f, qz = 0.f;
    if (active) {
        qx = q_xyz[3 * q]; qy = q_xyz[3 * q + 1]; qz = q_xyz[3 * q + 2];
    }

    // loop over db tiles (single iteration when P <= TILE)
    for (int base = 0; base < ndb; base += TILE) {
        const int cnt  = min(TILE, ndb - base);
        const int cntp = (cnt + 7) & ~7;   // pad to unroll multiple with sentinels
        __syncthreads();                   // protect previous tile contents
        for (int j = tid; j < cntp; j += THREADS) {
            float px, py, pz;
            const int gj = base + j;
            if (j < cnt) {
                const float x = d_xyzp[3 * gj];
                const float y = d_xyzp[3 * gj + 1];
                const float z = d_xyzp[3 * gj + 2];
                px = fmaf(r00, x, fmaf(r01, y, fmaf(r02, z, t0)));
                py = fmaf(r10, x, fmaf(r11, y, fmaf(r12_, z, t1)));
                pz = fmaf(r20, x, fmaf(r21_, y, fmaf(r22, z, t2)));
            } else {
                px = py = pz = 1.0e15f;    // sentinel: huge but finite distance
            }
            tile[j] = make_float4(px, py, pz, 0.0f);
        }
        __syncthreads();

        if (active) {
            for (int j0 = 0; j0 < cntp; j0 += 8) {
                #pragma unroll
                for (int u = 0; u < 8; ++u) {
                    const float4 p = tile[j0 + u];
                    const float dx = qx - p.x;
                    const float dy = qy - p.y;
                    const float dz = qz - p.z;
                    const float d2 = fmaf(dx, dx, fmaf(dy, dy, dz * dz));
                    if (d2 < kd[KNN - 1]) {
                        const int jj = base + j0 + u;
                        bool mn = true;   // m_{s+1}; true at s=KNN-1 (d2 < old kd[19])
                        #pragma unroll
                        for (int s = KNN - 1; s >= 1; --s) {
                            const bool m = d2 < kd[s - 1];
                            const float nd = m ? kd[s - 1] : (mn ? d2 : kd[s]);
                            const int   ni = m ? ki[s - 1] : (mn ? jj : ki[s]);
                            kd[s] = nd; ki[s] = ni; mn = m;
                        }
                        if (mn) { kd[0] = d2; ki[0] = jj; }
                    }
                }
            }
        }
    }

    // ---- epilogue: weights over the K neighbors ----
    float acc = 0.0f;
    if (active) {
        const float ell = fmaxf(0.15f * (qz - 10.0f) * 0.1f, 0.15f);
        const float inv_ls = 1.0f / (ell * ell);
        const float hq0 = q_hsv[3 * q], hq1 = q_hsv[3 * q + 1], hq2 = q_hsv[3 * q + 2];
        const float n0 = q_nrm[3 * q], n1 = q_nrm[3 * q + 1], n2 = q_nrm[3 * q + 2];
        const float rq = q_res[q];
        // R^T * n_q, so that dot with RAW db normal equals n_q . (R n_db)
        const float tn0 = r00 * n0 + r10 * n1 + r20 * n2;
        const float tn1 = r01 * n0 + r11 * n1 + r21_ * n2;
        const float tn2 = r02 * n0 + r12_ * n1 + r22 * n2;
        #pragma unroll
        for (int k = 0; k < KNN; ++k) {
            const int j = ki[k];
            const float wd = expf(-kd[k] * inv_ls);
            const float h0 = d_hsv[3 * j]     - hq0;
            const float h1 = d_hsv[3 * j + 1] - hq1;
            const float h2 = d_hsv[3 * j + 2] - hq2;
            const float cd = sqrtf(fmaf(h0, h0, fmaf(h1, h1, h2 * h2)) + 1e-12f);
            const float wc = expf(-cd * 5.0f);            // 1/COLOR_SCALE = 5
            const float rk = d_res[j];
            const float alpha = 0.2f / (0.1f + rq + rk);  // 2*RES_MIN/(2*RES_MIN/RES_MAX + rq + rk)
            const float dn = tn0 * d_nrm[3 * j] + tn1 * d_nrm[3 * j + 1] + tn2 * d_nrm[3 * j + 2];
            const float wn = fmaxf(dn * alpha, 0.0f);
            acc += wd * wc * wn;
        }
    }

    // ---- deterministic block reduction ----
    __shared__ float red[THREADS];
    red[tid] = acc;
    __syncthreads();
    #pragma unroll
    for (int s = THREADS / 2; s > 0; s >>= 1) {
        if (tid < s) red[tid] += red[tid + s];
        __syncthreads();
    }
    if (tid == 0) {
        const int bid = (side * gridDim.y + b) * gridDim.x + chunk;
        g_partials[bid] = red[0];
    }
}

__global__ void finalize_kernel(const int* __restrict__ npts1,
                                const int* __restrict__ npts2,
                                float* __restrict__ out,
                                int B, int nblk_side, int out_size)
{
    if (threadIdx.x == 0 && blockIdx.x == 0) {
        double s0 = 0.0, s1 = 0.0;
        for (int i = 0; i < nblk_side; ++i) {
            s0 += (double)g_partials[i];
            s1 += (double)g_partials[nblk_side + i];
        }
        double c1 = 0.0, c2 = 0.0;
        for (int i = 0; i < B; ++i) { c1 += npts1[i]; c2 += npts2[i]; }
        const double k1 = s0 / (c1 * (double)KNN);
        const double k2 = s1 / (c2 * (double)KNN);
        out[0] = (float)(0.5 * (k1 + k2));
        for (int i = 1; i < out_size; ++i) out[i] = 0.0f;
    }
}

extern "C" void kernel_launch(void* const* d_in, const int* in_sizes, int n_in,
                              void* d_out, int out_size)
{
    const float* xyz1 = (const float*)d_in[0];
    const float* xyz2 = (const float*)d_in[1];
    const float* hsv1 = (const float*)d_in[2];
    const float* hsv2 = (const float*)d_in[3];
    const float* nrm1 = (const float*)d_in[4];
    const float* nrm2 = (const float*)d_in[5];
    const float* res1 = (const float*)d_in[6];
    const float* res2 = (const float*)d_in[7];
    const float* R12  = (const float*)d_in[8];
    const float* t12  = (const float*)d_in[9];
    const float* R21  = (const float*)d_in[10];
    const float* t21  = (const float*)d_in[11];
    const int* npts1  = (const int*)d_in[12];
    const int* npts2  = (const int*)d_in[13];

    const int B = in_sizes[12];
    const int P = in_sizes[0] / (3 * B);
    const int chunks = (P + THREADS - 1) / THREADS;
    const int tile_pts = (P < TILE ? ((P + 7) & ~7) : TILE);
    const size_t smem = (size_t)tile_pts * sizeof(float4);

    static bool attr_set = false;
    // (idempotent; harmless to call every launch — not a stream op, not captured)
    cudaFuncSetAttribute(knn_kernel, cudaFuncAttributeMaxDynamicSharedMemorySize, (int)smem);
    (void)attr_set;

    dim3 grid(chunks, B, 2);
    knn_kernel<<<grid, THREADS, smem>>>(xyz1, xyz2, hsv1, hsv2, nrm1, nrm2,
                                        res1, res2, R12, t12, R21, t21,
                                        npts1, npts2, B, P);
    finalize_kernel<<<1, 32>>>(npts1, npts2, (float*)d_out, B, B * chunks, out_size);
}

// round 3
// speedup vs baseline: 1.2275x; 1.2275x over previous
#include <cuda_runtime.h>
#include <math.h>

#define KNN 20
#define THREADS 256
#define TILE 8192            // db points per smem tile
#define CAP 64               // per-thread candidate buffer entries
#define STEP 16              // candidates per drain-check
#define IDXMASK 0x1FFFu      // 13 bits: P <= 8192
#define KEYMASK 0xFFFFE000u

__device__ float g_partials[1024];

__device__ __forceinline__ void bubble20(unsigned (&kd)[KNN], unsigned v) {
#pragma unroll
    for (int s = 0; s < KNN; ++s) {
        unsigned lo = min(kd[s], v);   // unsigned min/max
        v = max(kd[s], v);
        kd[s] = lo;
    }
}

__global__ void __launch_bounds__(THREADS, 1) knn_kernel(
    const float* __restrict__ xyz1, const float* __restrict__ xyz2,
    const float* __restrict__ hsv1, const float* __restrict__ hsv2,
    const float* __restrict__ nrm1, const float* __restrict__ nrm2,
    const float* __restrict__ res1, const float* __restrict__ res2,
    const float* __restrict__ R12,  const float* __restrict__ t12,
    const float* __restrict__ R21,  const float* __restrict__ t21,
    const int* __restrict__ npts1,  const int* __restrict__ npts2,
    int B, int P)
{
    extern __shared__ float4 smem[];
    float4*   tile = smem;                                  // TILE float4 = 128KB
    unsigned* buf  = (unsigned*)(smem + TILE);              // THREADS*CAP u32 = 64KB

    const int side  = blockIdx.z;
    const int b     = blockIdx.y;
    const int chunk = blockIdx.x;
    const int tid   = threadIdx.x;

    const float *q_xyz, *q_hsv, *q_nrm, *q_res;
    const float *d_xyzp, *d_hsv, *d_nrm, *d_res;
    const float *R, *T;
    int nq, ndb;
    const size_t o3 = (size_t)b * P * 3;
    const size_t o1 = (size_t)b * P;
    if (side == 0) {
        q_xyz = xyz1 + o3; q_hsv = hsv1 + o3; q_nrm = nrm1 + o3; q_res = res1 + o1;
        d_xyzp = xyz2 + o3; d_hsv = hsv2 + o3; d_nrm = nrm2 + o3; d_res = res2 + o1;
        R = R12 + b * 9; T = t12 + b * 3;
        nq = npts1[b]; ndb = npts2[b];
    } else {
        q_xyz = xyz2 + o3; q_hsv = hsv2 + o3; q_nrm = nrm2 + o3; q_res = res2 + o1;
        d_xyzp = xyz1 + o3; d_hsv = hsv1 + o3; d_nrm = nrm1 + o3; d_res = res1 + o1;
        R = R21 + b * 9; T = t21 + b * 3;
        nq = npts2[b]; ndb = npts1[b];
    }

    const float r00 = R[0], r01 = R[1], r02 = R[2];
    const float r10 = R[3], r11 = R[4], r12_ = R[5];
    const float r20 = R[6], r21_ = R[7], r22 = R[8];
    const float t0 = T[0], t1 = T[1], t2 = T[2];

    const int q = chunk * THREADS + tid;
    const bool active = (q < nq);

    // ---- stage db tile: transform while loading, pack idx into .w ----
    const int cnt  = (ndb < TILE) ? ndb : TILE;             // single tile (P<=8192)
    const int cntp = (cnt + STEP - 1) & ~(STEP - 1);
    for (int j = tid; j < cntp; j += THREADS) {
        float px, py, pz;
        if (j < cnt) {
            const float x = d_xyzp[3 * j];
            const float y = d_xyzp[3 * j + 1];
            const float z = d_xyzp[3 * j + 2];
            px = fmaf(r00, x, fmaf(r01, y, fmaf(r02, z, t0)));
            py = fmaf(r10, x, fmaf(r11, y, fmaf(r12_, z, t1)));
            pz = fmaf(r20, x, fmaf(r21_, y, fmaf(r22, z, t2)));
        } else {
            px = py = pz = 1.0e15f;                         // sentinel, never selected
        }
        tile[j] = make_float4(px, py, pz, __uint_as_float((unsigned)j));
    }
    __syncthreads();

    float qx = 1.0e15f, qy = 1.0e15f, qz = 1.0e15f;
    if (active) {
        qx = q_xyz[3 * q]; qy = q_xyz[3 * q + 1]; qz = q_xyz[3 * q + 2];
    }

    unsigned kd[KNN];
#pragma unroll
    for (int s = 0; s < KNN; ++s) kd[s] = 0xFFFFFFFFu;

    unsigned thr = active ? 0xFFFFFFFFu : 0u;
    unsigned* const mybase = buf + tid;                     // stride THREADS: conflict-free
    unsigned*       wp     = mybase;
    unsigned* const wlimit = mybase + (CAP - STEP) * THREADS;

    // ---- scan: fully predicated hot loop; rare warp-collective drains ----
    for (int j0 = 0; j0 < cntp; j0 += STEP) {
        if (__any_sync(0xFFFFFFFFu, wp >= wlimit)) {
            for (unsigned* rp = mybase; rp < wp; rp += THREADS) {
                const unsigned v = *rp;
                if (v < kd[KNN - 1]) bubble20(kd, v);
            }
            wp = mybase;
            thr = active ? kd[KNN - 1] : 0u;
        }
#pragma unroll
        for (int u = 0; u < STEP; ++u) {
            const float4 p = tile[j0 + u];
            const float dx = qx - p.x;
            const float dy = qy - p.y;
            const float dz = qz - p.z;
            const float d2 = fmaf(dx, dx, fmaf(dy, dy, dz * dz));
            const unsigned key = (__float_as_uint(d2) & KEYMASK) | __float_as_uint(p.w);
            if (key < thr) { *wp = key; wp += THREADS; }    // predicated push
        }
    }
    // final drain
    for (unsigned* rp = mybase; rp < wp; rp += THREADS) {
        const unsigned v = *rp;
        if (v < kd[KNN - 1]) bubble20(kd, v);
    }

    // ---- epilogue: exact d2 recomputed from tile; weights over K neighbors ----
    float acc = 0.0f;
    if (active) {
        const float ell = fmaxf(0.15f * (qz - 10.0f) * 0.1f, 0.15f);
        const float inv_ls = 1.0f / (ell * ell);
        const float hq0 = q_hsv[3 * q], hq1 = q_hsv[3 * q + 1], hq2 = q_hsv[3 * q + 2];
        const float n0 = q_nrm[3 * q], n1 = q_nrm[3 * q + 1], n2 = q_nrm[3 * q + 2];
        const float rq = q_res[q];
        // R^T * n_q so dot with RAW db normal equals n_q . (R n_db)
        const float tn0 = r00 * n0 + r10 * n1 + r20 * n2;
        const float tn1 = r01 * n0 + r11 * n1 + r21_ * n2;
        const float tn2 = r02 * n0 + r12_ * n1 + r22 * n2;
#pragma unroll
        for (int k = 0; k < KNN; ++k) {
            const int j = (int)(kd[k] & IDXMASK);
            const float4 p = tile[j];
            const float dx = qx - p.x, dy = qy - p.y, dz = qz - p.z;
            const float d2 = fmaf(dx, dx, fmaf(dy, dy, dz * dz));   // exact
            const float wd = expf(-d2 * inv_ls);
            const float h0 = d_hsv[3 * j]     - hq0;
            const float h1 = d_hsv[3 * j + 1] - hq1;
            const float h2 = d_hsv[3 * j + 2] - hq2;
            const float cd = sqrtf(fmaf(h0, h0, fmaf(h1, h1, h2 * h2)) + 1e-12f);
            const float wc = expf(-cd * 5.0f);
            const float rk = d_res[j];
            const float alpha = 0.2f / (0.1f + rq + rk);
            const float dn = tn0 * d_nrm[3 * j] + tn1 * d_nrm[3 * j + 1] + tn2 * d_nrm[3 * j + 2];
            const float wn = fmaxf(dn * alpha, 0.0f);
            acc += wd * wc * wn;
        }
    }

    // ---- deterministic block reduction ----
    __shared__ float red[THREADS];
    red[tid] = acc;
    __syncthreads();
#pragma unroll
    for (int s = THREADS / 2; s > 0; s >>= 1) {
        if (tid < s) red[tid] += red[tid + s];
        __syncthreads();
    }
    if (tid == 0) {
        const int bid = (side * gridDim.y + b) * gridDim.x + chunk;
        g_partials[bid] = red[0];
    }
}

__global__ void finalize_kernel(const int* __restrict__ npts1,
                                const int* __restrict__ npts2,
                                float* __restrict__ out,
                                int B, int nblk_side, int out_size)
{
    __shared__ double sh0[256], sh1[256];
    const int tid = threadIdx.x;
    double a0 = 0.0, a1 = 0.0;
    for (int i = tid; i < nblk_side; i += 256) {
        a0 += (double)g_partials[i];
        a1 += (double)g_partials[nblk_side + i];
    }
    sh0[tid] = a0; sh1[tid] = a1;
    __syncthreads();
#pragma unroll
    for (int s = 128; s > 0; s >>= 1) {
        if (tid < s) { sh0[tid] += sh0[tid + s]; sh1[tid] += sh1[tid + s]; }
        __syncthreads();
    }
    if (tid == 0) {
        double c1 = 0.0, c2 = 0.0;
        for (int i = 0; i < B; ++i) { c1 += npts1[i]; c2 += npts2[i]; }
        const double k1 = sh0[0] / (c1 * (double)KNN);
        const double k2 = sh1[0] / (c2 * (double)KNN);
        out[0] = (float)(0.5 * (k1 + k2));
        for (int i = 1; i < out_size; ++i) out[i] = 0.0f;
    }
}

extern "C" void kernel_launch(void* const* d_in, const int* in_sizes, int n_in,
                              void* d_out, int out_size)
{
    const float* xyz1 = (const float*)d_in[0];
    const float* xyz2 = (const float*)d_in[1];
    const float* hsv1 = (const float*)d_in[2];
    const float* hsv2 = (const float*)d_in[3];
    const float* nrm1 = (const float*)d_in[4];
    const float* nrm2 = (const float*)d_in[5];
    const float* res1 = (const float*)d_in[6];
    const float* res2 = (const float*)d_in[7];
    const float* R12  = (const float*)d_in[8];
    const float* t12  = (const float*)d_in[9];
    const float* R21  = (const float*)d_in[10];
    const float* t21  = (const float*)d_in[11];
    const int* npts1  = (const int*)d_in[12];
    const int* npts2  = (const int*)d_in[13];

    const int B = in_sizes[12];
    const int P = in_sizes[0] / (3 * B);
    const int chunks = (P + THREADS - 1) / THREADS;
    const size_t smem = (size_t)TILE * sizeof(float4) + (size_t)THREADS * CAP * sizeof(unsigned);

    cudaFuncSetAttribute(knn_kernel, cudaFuncAttributeMaxDynamicSharedMemorySize, (int)smem);

    dim3 grid(chunks, B, 2);
    knn_kernel<<<grid, THREADS, smem>>>(xyz1, xyz2, hsv1, hsv2, nrm1, nrm2,
                                        res1, res2, R12, t12, R21, t21,
                                        npts1, npts2, B, P);
    finalize_kernel<<<1, 256>>>(npts1, npts2, (float*)d_out, B, B * chunks, out_size);
}

// round 7
// speedup vs baseline: 2.2183x; 1.8072x over previous
#include <cuda_runtime.h>
#include <math.h>

#define KNN 20
#define THREADS 256
#define TILE 8192            // db points per smem tile
#define CAP 64               // per-thread candidate buffer entries
#define STEP 16              // candidates per drain-check
#define IDXMASK 0x1FFFu      // 13 bits: P <= 8192
#define KEYMASK 0xFFFFE000u

__device__ float g_partials[1024];

__device__ __forceinline__ void bubble20(unsigned (&kd)[KNN], unsigned v) {
#pragma unroll
    for (int s = 0; s < KNN; ++s) {
        unsigned lo = min(kd[s], v);   // unsigned min/max
        v = max(kd[s], v);
        kd[s] = lo;
    }
}

__global__ void dummy_kernel() {}

__global__ void __launch_bounds__(THREADS, 1) knn_kernel(
    const float* __restrict__ xyz1, const float* __restrict__ xyz2,
    const float* __restrict__ hsv1, const float* __restrict__ hsv2,
    const float* __restrict__ nrm1, const float* __restrict__ nrm2,
    const float* __restrict__ res1, const float* __restrict__ res2,
    const float* __restrict__ R12,  const float* __restrict__ t12,
    const float* __restrict__ R21,  const float* __restrict__ t21,
    const int* __restrict__ npts1,  const int* __restrict__ npts2,
    int B, int P)
{
    extern __shared__ float4 smem[];
    float4*   tile = smem;                                  // TILE float4 = 128KB
    unsigned* buf  = (unsigned*)(smem + TILE);              // THREADS*CAP u32 = 64KB

    const int side  = blockIdx.z;
    const int b     = blockIdx.y;
    const int chunk = blockIdx.x;
    const int tid   = threadIdx.x;

    const float *q_xyz, *q_hsv, *q_nrm, *q_res;
    const float *d_xyzp, *d_hsv, *d_nrm, *d_res;
    const float *R, *T;
    int nq, ndb;
    const size_t o3 = (size_t)b * P * 3;
    const size_t o1 = (size_t)b * P;
    if (side == 0) {
        q_xyz = xyz1 + o3; q_hsv = hsv1 + o3; q_nrm = nrm1 + o3; q_res = res1 + o1;
        d_xyzp = xyz2 + o3; d_hsv = hsv2 + o3; d_nrm = nrm2 + o3; d_res = res2 + o1;
        R = R12 + b * 9; T = t12 + b * 3;
        nq = npts1[b]; ndb = npts2[b];
    } else {
        q_xyz = xyz2 + o3; q_hsv = hsv2 + o3; q_nrm = nrm2 + o3; q_res = res2 + o1;
        d_xyzp = xyz1 + o3; d_hsv = hsv1 + o3; d_nrm = nrm1 + o3; d_res = res1 + o1;
        R = R21 + b * 9; T = t21 + b * 3;
        nq = npts2[b]; ndb = npts1[b];
    }

    const float r00 = R[0], r01 = R[1], r02 = R[2];
    const float r10 = R[3], r11 = R[4], r12_ = R[5];
    const float r20 = R[6], r21_ = R[7], r22 = R[8];
    const float t0 = T[0], t1 = T[1], t2 = T[2];

    const int q = chunk * THREADS + tid;
    const bool active = (q < nq);

    // ---- stage db tile: transform while loading, pack idx into .w ----
    const int cnt  = (ndb < TILE) ? ndb : TILE;             // single tile (P<=8192)
    const int cntp = (cnt + STEP - 1) & ~(STEP - 1);
    for (int j = tid; j < cntp; j += THREADS) {
        float px, py, pz;
        if (j < cnt) {
            const float x = d_xyzp[3 * j];
            const float y = d_xyzp[3 * j + 1];
            const float z = d_xyzp[3 * j + 2];
            px = fmaf(r00, x, fmaf(r01, y, fmaf(r02, z, t0)));
            py = fmaf(r10, x, fmaf(r11, y, fmaf(r12_, z, t1)));
            pz = fmaf(r20, x, fmaf(r21_, y, fmaf(r22, z, t2)));
        } else {
            px = py = pz = 1.0e15f;                         // sentinel, never selected
        }
        tile[j] = make_float4(px, py, pz, __uint_as_float((unsigned)j));
    }
    __syncthreads();

    float qx = 1.0e15f, qy = 1.0e15f, qz = 1.0e15f;
    if (active) {
        qx = q_xyz[3 * q]; qy = q_xyz[3 * q + 1]; qz = q_xyz[3 * q + 2];
    }

    unsigned kd[KNN];
#pragma unroll
    for (int s = 0; s < KNN; ++s) kd[s] = 0xFFFFFFFFu;

    unsigned thr = active ? 0xFFFFFFFFu : 0u;
    unsigned* const mybase = buf + tid;                     // stride THREADS: conflict-free
    unsigned*       wp     = mybase;
    unsigned* const wlimit = mybase + (CAP - STEP) * THREADS;

    // ---- scan: phase-split (loads batched, pushes separate); rare drains ----
    for (int j0 = 0; j0 < cntp; j0 += STEP) {
        if (__any_sync(0xFFFFFFFFu, wp >= wlimit)) {
            for (unsigned* rp = mybase; rp < wp; rp += THREADS) {
                const unsigned v = *rp;
                if (v < kd[KNN - 1]) bubble20(kd, v);
            }
            wp = mybase;
            thr = active ? kd[KNN - 1] : 0u;
        }
        // Phase A: 16 independent distance/key computations (LDS batch, no STS)
        unsigned keys[STEP];
#pragma unroll
        for (int u = 0; u < STEP; ++u) {
            const float4 p = tile[j0 + u];
            const float dx = qx - p.x;
            const float dy = qy - p.y;
            const float dz = qz - p.z;
            const float d2 = fmaf(dx, dx, fmaf(dy, dy, dz * dz));
            keys[u] = (__float_as_uint(d2) & KEYMASK) | __float_as_uint(p.w);
        }
        // Phase B: predicated pushes only
#pragma unroll
        for (int u = 0; u < STEP; ++u) {
            if (keys[u] < thr) { *wp = keys[u]; wp += THREADS; }
        }
    }
    // final drain
    for (unsigned* rp = mybase; rp < wp; rp += THREADS) {
        const unsigned v = *rp;
        if (v < kd[KNN - 1]) bubble20(kd, v);
    }

    // ---- epilogue: exact d2 recomputed from tile; weights over K neighbors ----
    float acc = 0.0f;
    if (active) {
        const float ell = fmaxf(0.15f * (qz - 10.0f) * 0.1f, 0.15f);
        const float inv_ls = 1.0f / (ell * ell);
        const float hq0 = q_hsv[3 * q], hq1 = q_hsv[3 * q + 1], hq2 = q_hsv[3 * q + 2];
        const float n0 = q_nrm[3 * q], n1 = q_nrm[3 * q + 1], n2 = q_nrm[3 * q + 2];
        const float rq = q_res[q];
        // R^T * n_q so dot with RAW db normal equals n_q . (R n_db)
        const float tn0 = r00 * n0 + r10 * n1 + r20 * n2;
        const float tn1 = r01 * n0 + r11 * n1 + r21_ * n2;
        const float tn2 = r02 * n0 + r12_ * n1 + r22 * n2;
#pragma unroll
        for (int k = 0; k < KNN; ++k) {
            const int j = (int)(kd[k] & IDXMASK);
            const float4 p = tile[j];
            const float dx = qx - p.x, dy = qy - p.y, dz = qz - p.z;
            const float d2 = fmaf(dx, dx, fmaf(dy, dy, dz * dz));   // exact
            const float wd = expf(-d2 * inv_ls);
            const float h0 = d_hsv[3 * j]     - hq0;
            const float h1 = d_hsv[3 * j + 1] - hq1;
            const float h2 = d_hsv[3 * j + 2] - hq2;
            const float cd = sqrtf(fmaf(h0, h0, fmaf(h1, h1, h2 * h2)) + 1e-12f);
            const float wc = expf(-cd * 5.0f);
            const float rk = d_res[j];
            const float alpha = 0.2f / (0.1f + rq + rk);
            const float dn = tn0 * d_nrm[3 * j] + tn1 * d_nrm[3 * j + 1] + tn2 * d_nrm[3 * j + 2];
            const float wn = fmaxf(dn * alpha, 0.0f);
            acc += wd * wc * wn;
        }
    }

    // ---- deterministic block reduction ----
    __shared__ float red[THREADS];
    red[tid] = acc;
    __syncthreads();
#pragma unroll
    for (int s = THREADS / 2; s > 0; s >>= 1) {
        if (tid < s) red[tid] += red[tid + s];
        __syncthreads();
    }
    if (tid == 0) {
        const int bid = (side * gridDim.y + b) * gridDim.x + chunk;
        g_partials[bid] = red[0];
    }
}

__global__ void finalize_kernel(const int* __restrict__ npts1,
                                const int* __restrict__ npts2,
                                float* __restrict__ out,
                                int B, int nblk_side, int out_size)
{
    __shared__ double sh0[256], sh1[256];
    const int tid = threadIdx.x;
    double a0 = 0.0, a1 = 0.0;
    for (int i = tid; i < nblk_side; i += 256) {
        a0 += (double)g_partials[i];
        a1 += (double)g_partials[nblk_side + i];
    }
    sh0[tid] = a0; sh1[tid] = a1;
    __syncthreads();
#pragma unroll
    for (int s = 128; s > 0; s >>= 1) {
        if (tid < s) { sh0[tid] += sh0[tid + s]; sh1[tid] += sh1[tid + s]; }
        __syncthreads();
    }
    if (tid == 0) {
        double c1 = 0.0, c2 = 0.0;
        for (int i = 0; i < B; ++i) { c1 += npts1[i]; c2 += npts2[i]; }
        const double k1 = sh0[0] / (c1 * (double)KNN);
        const double k2 = sh1[0] / (c2 * (double)KNN);
        out[0] = (float)(0.5 * (k1 + k2));
        for (int i = 1; i < out_size; ++i) out[i] = 0.0f;
    }
}

extern "C" void kernel_launch(void* const* d_in, const int* in_sizes, int n_in,
                              void* d_out, int out_size)
{
    const float* xyz1 = (const float*)d_in[0];
    const float* xyz2 = (const float*)d_in[1];
    const float* hsv1 = (const float*)d_in[2];
    const float* hsv2 = (const float*)d_in[3];
    const float* nrm1 = (const float*)d_in[4];
    const float* nrm2 = (const float*)d_in[5];
    const float* res1 = (const float*)d_in[6];
    const float* res2 = (const float*)d_in[7];
    const float* R12  = (const float*)d_in[8];
    const float* t12  = (const float*)d_in[9];
    const float* R21  = (const float*)d_in[10];
    const float* t21  = (const float*)d_in[11];
    const int* npts1  = (const int*)d_in[12];
    const int* npts2  = (const int*)d_in[13];

    const int B = in_sizes[12];
    const int P = in_sizes[0] / (3 * B);
    const int chunks = (P + THREADS - 1) / THREADS;
    const size_t smem = (size_t)TILE * sizeof(float4) + (size_t)THREADS * CAP * sizeof(unsigned);

    cudaFuncSetAttribute(knn_kernel, cudaFuncAttributeMaxDynamicSharedMemorySize, (int)smem);

    dim3 grid(chunks, B, 2);
    // Launch pattern [dummy, knn, dummy, finalize]: 4 launches/replay puts
    // global launch index 5 (ncu -s 5 -c 1) on knn_kernel of replay 2,
    // so the profile finally captures the hot kernel.
    dummy_kernel<<<1, 32>>>();
    knn_kernel<<<grid, THREADS, smem>>>(xyz1, xyz2, hsv1, hsv2, nrm1, nrm2,
                                        res1, res2, R12, t12, R21, t21,
                                        npts1, npts2, B, P);
    dummy_kernel<<<1, 32>>>();
    finalize_kernel<<<1, 256>>>(npts1, npts2, (float*)d_out, B, B * chunks, out_size);
}